// round 12
// baseline (speedup 1.0000x reference)
#include <cuda_runtime.h>
#include <cstdint>

// ---------------- scratch (no allocations allowed) ----------------
__device__ float g_WqEffT[512 * 512];   // [n=h*64+e][k]
__device__ float g_WkEffT[512 * 512];
__device__ float g_WkT[512 * 512];
__device__ float g_WoT[512 * 512];
__device__ float g_biasQ[512];
__device__ float g_biasK[512];
__device__ float g_qhE[16 * 64 * 512];   // [z][e][t]
__device__ float g_khbE[16 * 64 * 512];  // [z][e][s]
__device__ float g_KpR[16 * 512 * 64];   // [z][s][d]
__device__ float g_merged[1024 * 512];   // [b*512+t][h*64+d]

__device__ __forceinline__ uint32_t f2tf32(float x) {
    uint32_t u;
    asm("cvt.rna.tf32.f32 %0, %1;" : "=r"(u) : "f"(x));
    return u;
}
__device__ __forceinline__ float tanh_fast(float x) {
    float y;
    asm("tanh.approx.f32 %0, %1;" : "=f"(y) : "f"(x));
    return y;
}
__device__ __forceinline__ void mma_m16n8k8(float* d, const uint32_t* a,
                                            const uint32_t* b) {
    asm volatile(
        "mma.sync.aligned.m16n8k8.row.col.f32.tf32.tf32.f32 "
        "{%0,%1,%2,%3}, {%4,%5,%6,%7}, {%8,%9}, {%0,%1,%2,%3};"
        : "+f"(d[0]), "+f"(d[1]), "+f"(d[2]), "+f"(d[3])
        : "r"(a[0]), "r"(a[1]), "r"(a[2]), "r"(a[3]), "r"(b[0]), "r"(b[1]));
}

// ==================== merged prep kernel ====================
__global__ void __launch_bounds__(256) prep_all(
    const float* __restrict__ bq, const float* __restrict__ Wq_h,
    const float* __restrict__ bk, const float* __restrict__ Wk_h,
    const float* __restrict__ b_h, const float* __restrict__ Wq,
    const float* __restrict__ Wk, const float* __restrict__ Wo) {
    __shared__ float sm[2][64][68];
    const int bx = blockIdx.x, tid = threadIdx.x;
    if (bx < 4) {
        int i = bx * 256 + tid;
        int side = i >> 9, col = i & 511, h = col >> 6, e = col & 63;
        const float* bb = side ? bk : bq;
        const float* Wh = (side ? Wk_h : Wq_h) + h * 4096;
        float s = 0.f;
#pragma unroll 8
        for (int d = 0; d < 64; d++) s += bb[h * 64 + d] * Wh[d * 64 + e];
        if (side) g_biasK[col] = s + b_h[col];
        else      g_biasQ[col] = s;
    } else if (bx < 132) {
        int q = bx - 4;
        int side = q >> 6;
        q &= 63;
        int h = q >> 3, k0 = (q & 7) * 64;
        const float* W = side ? Wk : Wq;
        const float* Wh = (side ? Wk_h : Wq_h) + h * 4096;
        float* C = (side ? g_WkEffT : g_WqEffT) + h * 64 * 512;
#pragma unroll
        for (int r = 0; r < 4; r++) {
            int idx = tid + r * 256;
            int row = idx >> 4, c4 = (idx & 15) << 2;
            *(float4*)&sm[0][row][c4] = *(const float4*)&W[(long)(k0 + row) * 512 + h * 64 + c4];
            *(float4*)&sm[1][row][c4] = *(const float4*)&Wh[row * 64 + c4];
        }
        __syncthreads();
        const int tmm = (tid >> 4) * 4, tnn = (tid & 15) * 4;
        float acc[4][4] = {};
#pragma unroll 8
        for (int d = 0; d < 64; d++) {
            float a[4], b[4];
#pragma unroll
            for (int i = 0; i < 4; i++) a[i] = sm[0][tmm + i][d];
            *(float4*)b = *(const float4*)&sm[1][d][tnn];
#pragma unroll
            for (int i = 0; i < 4; i++)
#pragma unroll
                for (int j = 0; j < 4; j++) acc[i][j] += a[i] * b[j];
        }
#pragma unroll
        for (int i = 0; i < 4; i++)
#pragma unroll
            for (int j = 0; j < 4; j++)
                C[(long)(tnn + j) * 512 + k0 + tmm + i] = acc[i][j];
    } else {
        int q = bx - 132;
        int zz = q >> 8;
        q &= 255;
        int by = q >> 4, bxx = q & 15;
        const float* S = zz ? Wo : Wk;
        float* D = zz ? g_WoT : g_WkT;
        float (*t)[33] = (float(*)[33]) & sm[0][0][0];
        int lx = tid & 31, ly = tid >> 5;
        int x = bxx * 32 + lx, y0 = by * 32;
#pragma unroll
        for (int r = ly; r < 32; r += 8) t[r][lx] = S[(long)(y0 + r) * 512 + x];
        __syncthreads();
        int xo = y0 + lx;
#pragma unroll
        for (int r = ly; r < 32; r += 8) D[(long)(bxx * 32 + r) * 512 + xo] = t[lx][r];
    }
}

// ==================== tf32 mma.sync GEMM core ====================
// Double-buffered smem, 2-chunk-deep register prefetch. K-chunk 32.
// Tile MT x 64 (MT in {32,64}), 8 warps 2x4.
// C = A[Mx512] @ B^T (B K-major [512n][512k]) + bias.
// mode 0: row-major C. mode 1: [z][n&63][t] scatter. mode 2: [z][t][n&63].
template <int MT>
__device__ __forceinline__ void gemm_core(
    uint32_t* As, uint32_t* Bs,  // As: 2*(MT/16*4*128), Bs: 2*2048
    const float* __restrict__ A, const float* __restrict__ B,
    const float* __restrict__ bias, float* __restrict__ C,
    int m0, int n0, int mode) {
    constexpr int MI = MT / 32;          // mma m-tiles per warp
    constexpr int AR = MT / 32;          // A float4s per thread per chunk
    constexpr int ASTRIDE = (MT / 16) * 4 * 128;
    const int tid = threadIdx.x;
    const int wid = tid >> 5, lane = tid & 31;
    const int wm = wid >> 2, wn = wid & 3;

    float4 apf[2][AR], bpf[2][2];
    auto ldg = [&](int ch, int slot) {
        int k0 = ch << 5;
#pragma unroll
        for (int r = 0; r < AR; r++) {
            int j = tid + 256 * r;
            int row = j >> 3, c4 = (j & 7) << 2;
            apf[slot][r] = *(const float4*)&A[(long)(m0 + row) * 512 + k0 + c4];
        }
#pragma unroll
        for (int r = 0; r < 2; r++) {
            int j = tid + 256 * r;
            int row = j >> 3, c4 = (j & 7) << 2;
            bpf[slot][r] = *(const float4*)&B[(long)(n0 + row) * 512 + k0 + c4];
        }
    };
    auto sts = [&](int slot, int buf) {
#pragma unroll
        for (int r = 0; r < AR; r++) {
            int j = tid + 256 * r;
            int row = j >> 3, c4 = (j & 7) << 2;
            int ks = c4 >> 3, chi = (c4 >> 2) & 1;
            int mt = row >> 4, rlo = row & 15;
            int reg = (rlo >> 3) + (chi << 1);
            int off = buf * ASTRIDE + (mt * 4 + ks) * 128 + (rlo & 7) * 16 + reg;
            As[off + 0] = f2tf32(apf[slot][r].x);
            As[off + 4] = f2tf32(apf[slot][r].y);
            As[off + 8] = f2tf32(apf[slot][r].z);
            As[off + 12] = f2tf32(apf[slot][r].w);
        }
#pragma unroll
        for (int r = 0; r < 2; r++) {
            int j = tid + 256 * r;
            int row = j >> 3, c4 = (j & 7) << 2;
            int ks = c4 >> 3, chi = (c4 >> 2) & 1;
            int nt = row >> 3, g = row & 7;
            int off = buf * 2048 + (nt * 4 + ks) * 64 + g * 8 + chi;
            Bs[off + 0] = f2tf32(bpf[slot][r].x);
            Bs[off + 2] = f2tf32(bpf[slot][r].y);
            Bs[off + 4] = f2tf32(bpf[slot][r].z);
            Bs[off + 6] = f2tf32(bpf[slot][r].w);
        }
    };

    float acc[MI][2][4] = {};
    auto compute = [&](int buf) {
#pragma unroll
        for (int ks = 0; ks < 4; ks++) {
            uint32_t a[MI][4], b[2][2];
#pragma unroll
            for (int i = 0; i < MI; i++) {
                int mt = wm * MI + i;
                uint4 v = *(const uint4*)&As[buf * ASTRIDE + (mt * 4 + ks) * 128 + lane * 4];
                a[i][0] = v.x; a[i][1] = v.y; a[i][2] = v.z; a[i][3] = v.w;
            }
#pragma unroll
            for (int j = 0; j < 2; j++) {
                int nt = wn * 2 + j;
                uint2 v = *(const uint2*)&Bs[buf * 2048 + (nt * 4 + ks) * 64 + lane * 2];
                b[j][0] = v.x; b[j][1] = v.y;
            }
#pragma unroll
            for (int i = 0; i < MI; i++)
#pragma unroll
                for (int j = 0; j < 2; j++) mma_m16n8k8(acc[i][j], a[i], b[j]);
        }
    };

    // pipeline: ldg depth 2, smem depth 2
    ldg(0, 0);
    sts(0, 0);
    ldg(1, 1);
    __syncthreads();
    for (int ch = 0; ch < 16; ch++) {
        if (ch + 2 < 16) ldg(ch + 2, ch & 1);  // slot ch&1 was drained by sts last iter
        compute(ch & 1);
        if (ch + 1 < 16) sts((ch + 1) & 1, (ch + 1) & 1);
        __syncthreads();
    }

    const int g = lane >> 2, t4 = lane & 3;
#pragma unroll
    for (int i = 0; i < MI; i++)
#pragma unroll
        for (int j = 0; j < 2; j++) {
            int m = m0 + wm * (MI * 16) + i * 16 + g;
            int n = n0 + wn * 16 + j * 8 + t4 * 2;
            float c0 = acc[i][j][0], c1 = acc[i][j][1];
            float c2 = acc[i][j][2], c3 = acc[i][j][3];
            if (bias) {
                float b0 = bias[n], b1 = bias[n + 1];
                c0 += b0; c1 += b1; c2 += b0; c3 += b1;
            }
            if (mode == 0) {
                *(float2*)&C[(long)m * 512 + n] = make_float2(c0, c1);
                *(float2*)&C[(long)(m + 8) * 512 + n] = make_float2(c2, c3);
            } else if (mode == 1) {
                int bb = m >> 9, t = m & 511;
                long base0 = ((long)((bb << 3) + (n >> 6)) * 64 + (n & 63)) * 512;
                C[base0 + t] = c0;
                C[base0 + 512 + t] = c1;
                C[base0 + t + 8] = c2;
                C[base0 + 512 + t + 8] = c3;
            } else {
                int bb = m >> 9, t = m & 511;
                long r0 = ((long)((bb << 3) + (n >> 6)) * 512 + t) * 64 + (n & 63);
                *(float2*)&C[r0] = make_float2(c0, c1);
                *(float2*)&C[r0 + 8 * 64] = make_float2(c2, c3);
            }
        }
}

// three projections in one launch (z = task), 64x64 tiles (grid 384)
__global__ void __launch_bounds__(256) proj_mma(
    const float* __restrict__ query, const float* __restrict__ key,
    const float* __restrict__ bk) {
    __shared__ uint32_t As[2][2048], Bs[2][2048];  // 32 KB
    int task = blockIdx.z;
    int m0 = blockIdx.y * 64, n0 = blockIdx.x * 64;
    if (task == 0)
        gemm_core<64>(&As[0][0], &Bs[0][0], query, g_WqEffT, g_biasQ, g_qhE, m0, n0, 1);
    else if (task == 1)
        gemm_core<64>(&As[0][0], &Bs[0][0], key, g_WkEffT, g_biasK, g_khbE, m0, n0, 1);
    else
        gemm_core<64>(&As[0][0], &Bs[0][0], key, g_WkT, bk, g_KpR, m0, n0, 2);
}
// output projection, 32x64 tiles -> 256 CTAs
__global__ void __launch_bounds__(256) outg_mma(
    const float* __restrict__ bo, float* __restrict__ out) {
    __shared__ uint32_t As[2][1024], Bs[2][2048];  // 24 KB
    gemm_core<32>(&As[0][0], &Bs[0][0], g_merged, g_WoT, bo, out,
                  blockIdx.y * 32, blockIdx.x * 64, 0);
}

// ==================== fused score + online-softmax + deferred AV ====================
// grid (16 t-tiles, 16 z). Per CTA: rows t0..t0+31 of one (b,h).
// AV of chunk c-1 is interleaved into the score loop of chunk c (MUFU-shadow),
// reading P from pbuf (smem) and Kp rows straight from gmem (L1-broadcast).
__global__ void __launch_bounds__(256) fused_attn(const float* __restrict__ va) {
    const int t0 = blockIdx.x * 32;
    const int z = blockIdx.y;
    const int b = z >> 3, h = z & 7;
    __shared__ float qse[64][36];   // [e][t]
    __shared__ float kse[64][68];   // [e][s]
    __shared__ float pbuf[32][68];  // p of previous chunk [t][s]
    __shared__ float vsh[64];
    const int tid = threadIdx.x;
    const float* qbase = g_qhE + (long)z * 32768;
    const float* kbase = g_khbE + (long)z * 32768;
    const float* kpbase = g_KpR + (long)z * 32768;

#pragma unroll
    for (int r = 0; r < 2; r++) {
        int idx = tid + r * 256;
        int row = idx >> 3, c4 = (idx & 7) << 2;
        *(float4*)&qse[row][c4] = *(const float4*)&qbase[(long)row * 512 + t0 + c4];
    }
    if (tid < 64) vsh[tid] = va[h * 64 + tid];

    const int tm = (tid >> 4) * 2, tn = (tid & 15) * 4;
    float out[2][4] = {};
    float mrow[2] = {-1e30f, -1e30f};
    float lrow[2] = {0.f, 0.f};
    float sc[2][4];

    auto load_kse = [&](int c) {
        const int s0 = c * 64;
#pragma unroll
        for (int r = 0; r < 4; r++) {
            int idx = tid + r * 256;
            int row = idx >> 4, c4 = (idx & 15) << 2;
            *(float4*)&kse[row][c4] = *(const float4*)&kbase[(long)row * 512 + s0 + c4];
        }
    };
    auto softmax_step = [&]() {
        float rm[2], rs[2], alpha[2];
#pragma unroll
        for (int i = 0; i < 2; i++)
            rm[i] = fmaxf(fmaxf(sc[i][0], sc[i][1]), fmaxf(sc[i][2], sc[i][3]));
#pragma unroll
        for (int o = 8; o; o >>= 1) {
            rm[0] = fmaxf(rm[0], __shfl_xor_sync(0xffffffffu, rm[0], o));
            rm[1] = fmaxf(rm[1], __shfl_xor_sync(0xffffffffu, rm[1], o));
        }
#pragma unroll
        for (int i = 0; i < 2; i++) {
            float mn = fmaxf(mrow[i], rm[i]);
            alpha[i] = __expf(mrow[i] - mn);
            mrow[i] = mn;
#pragma unroll
            for (int j = 0; j < 4; j++) sc[i][j] = __expf(sc[i][j] - mn);
            rs[i] = (sc[i][0] + sc[i][1]) + (sc[i][2] + sc[i][3]);
        }
#pragma unroll
        for (int o = 8; o; o >>= 1) {
            rs[0] += __shfl_xor_sync(0xffffffffu, rs[0], o);
            rs[1] += __shfl_xor_sync(0xffffffffu, rs[1], o);
        }
#pragma unroll
        for (int i = 0; i < 2; i++) {
            lrow[i] = lrow[i] * alpha[i] + rs[i];
#pragma unroll
            for (int j = 0; j < 4; j++) out[i][j] *= alpha[i];
        }
    };
    auto store_p = [&]() {
        *(float4*)&pbuf[tm][tn] = make_float4(sc[0][0], sc[0][1], sc[0][2], sc[0][3]);
        *(float4*)&pbuf[tm + 1][tn] = make_float4(sc[1][0], sc[1][1], sc[1][2], sc[1][3]);
    };

    // ---- chunk 0: score only ----
    load_kse(0);
    __syncthreads();
    sc[0][0] = sc[0][1] = sc[0][2] = sc[0][3] = 0.f;
    sc[1][0] = sc[1][1] = sc[1][2] = sc[1][3] = 0.f;
#pragma unroll 4
    for (int e = 0; e < 64; e++) {
        float vv = vsh[e];
        float2 q2 = *(const float2*)&qse[e][tm];
        float4 kv = *(const float4*)&kse[e][tn];
        sc[0][0] += vv * tanh_fast(q2.x + kv.x);
        sc[0][1] += vv * tanh_fast(q2.x + kv.y);
        sc[0][2] += vv * tanh_fast(q2.x + kv.z);
        sc[0][3] += vv * tanh_fast(q2.x + kv.w);
        sc[1][0] += vv * tanh_fast(q2.y + kv.x);
        sc[1][1] += vv * tanh_fast(q2.y + kv.y);
        sc[1][2] += vv * tanh_fast(q2.y + kv.z);
        sc[1][3] += vv * tanh_fast(q2.y + kv.w);
    }
    softmax_step();
    store_p();

    // ---- chunks 1..7: score(c) + deferred AV(c-1) ----
    for (int c = 1; c < 8; c++) {
        __syncthreads();  // pbuf stores visible; kse reads of score(c-1) done
        load_kse(c);
        const float* kprev = kpbase + (long)(c - 1) * 64 * 64 + tn;
        __syncthreads();
        float ns[2][4] = {};
#pragma unroll 4
        for (int e = 0; e < 64; e++) {
            float vv = vsh[e];
            float2 q2 = *(const float2*)&qse[e][tm];
            float4 kv = *(const float4*)&kse[e][tn];
            ns[0][0] += vv * tanh_fast(q2.x + kv.x);
            ns[0][1] += vv * tanh_fast(q2.x + kv.y);
            ns[0][2] += vv * tanh_fast(q2.x + kv.z);
            ns[0][3] += vv * tanh_fast(q2.x + kv.w);
            ns[1][0] += vv * tanh_fast(q2.y + kv.x);
            ns[1][1] += vv * tanh_fast(q2.y + kv.y);
            ns[1][2] += vv * tanh_fast(q2.y + kv.z);
            ns[1][3] += vv * tanh_fast(q2.y + kv.w);
            // deferred AV for s = e of chunk c-1 (hidden in MUFU shadow)
            float p0 = pbuf[tm][e];
            float p1 = pbuf[tm + 1][e];
            float4 kp4 = *(const float4*)&kprev[(long)e * 64];
            out[0][0] += p0 * kp4.x; out[0][1] += p0 * kp4.y;
            out[0][2] += p0 * kp4.z; out[0][3] += p0 * kp4.w;
            out[1][0] += p1 * kp4.x; out[1][1] += p1 * kp4.y;
            out[1][2] += p1 * kp4.z; out[1][3] += p1 * kp4.w;
        }
#pragma unroll
        for (int i = 0; i < 2; i++)
#pragma unroll
            for (int j = 0; j < 4; j++) sc[i][j] = ns[i][j];
        softmax_step();      // scales out (incl. freshly added AV(c-1)) into new frame
        __syncthreads();     // AV reads of pbuf done (in score loop above)
        store_p();
    }

    // ---- drain AV(7) ----
    __syncthreads();
    {
        const float* kprev = kpbase + (long)7 * 64 * 64 + tn;
#pragma unroll 4
        for (int s = 0; s < 64; s++) {
            float p0 = pbuf[tm][s];
            float p1 = pbuf[tm + 1][s];
            float4 kp4 = *(const float4*)&kprev[(long)s * 64];
            out[0][0] += p0 * kp4.x; out[0][1] += p0 * kp4.y;
            out[0][2] += p0 * kp4.z; out[0][3] += p0 * kp4.w;
            out[1][0] += p1 * kp4.x; out[1][1] += p1 * kp4.y;
            out[1][2] += p1 * kp4.z; out[1][3] += p1 * kp4.w;
        }
    }

    float inv0 = __fdividef(1.f, lrow[0]);
    float inv1 = __fdividef(1.f, lrow[1]);
    long r0 = (long)(b * 512 + t0 + tm) * 512 + h * 64 + tn;
    *(float4*)&g_merged[r0] =
        make_float4(out[0][0] * inv0, out[0][1] * inv0, out[0][2] * inv0, out[0][3] * inv0);
    *(float4*)&g_merged[r0 + 512] =
        make_float4(out[1][0] * inv1, out[1][1] * inv1, out[1][2] * inv1, out[1][3] * inv1);
}

// ---------------- launcher ----------------
extern "C" void kernel_launch(void* const* d_in, const int* in_sizes, int n_in,
                              void* d_out, int out_size) {
    const float* query = (const float*)d_in[0];
    const float* key   = (const float*)d_in[1];
    const float* Wq   = (const float*)d_in[3];
    const float* bq   = (const float*)d_in[4];
    const float* Wk   = (const float*)d_in[5];
    const float* bk   = (const float*)d_in[6];
    const float* Wq_h = (const float*)d_in[9];
    const float* Wk_h = (const float*)d_in[10];
    const float* va_h = (const float*)d_in[11];
    const float* b_h  = (const float*)d_in[12];
    const float* Wo   = (const float*)d_in[13];
    const float* bo   = (const float*)d_in[14];
    float* out = (float*)d_out;

    prep_all<<<644, 256>>>(bq, Wq_h, bk, Wk_h, b_h, Wq, Wk, Wo);
    proj_mma<<<dim3(8, 16, 3), 256>>>(query, key, bk);
    fused_attn<<<dim3(16, 16), 256>>>(va_h);
    outg_mma<<<dim3(8, 32), 256>>>(bo, out);
}

// round 13
// speedup vs baseline: 1.2077x; 1.2077x over previous
#include <cuda_runtime.h>
#include <cstdint>

// ---------------- scratch (no allocations allowed) ----------------
__device__ float g_WqEffT[512 * 512];   // [n=h*64+e][k]
__device__ float g_WkEffT[512 * 512];
__device__ float g_WkT[512 * 512];
__device__ float g_WoT[512 * 512];
__device__ float g_biasQ[512];
__device__ float g_biasK[512];
__device__ float g_qhE[16 * 64 * 512];   // [z][e][t]
__device__ float g_khbE[16 * 64 * 512];  // [z][e][s]
__device__ float g_KpR[16 * 512 * 64];   // [z][s][d]
__device__ float g_merged[1024 * 512];   // [b*512+t][h*64+d]

__device__ __forceinline__ uint32_t f2tf32(float x) {
    uint32_t u;
    asm("cvt.rna.tf32.f32 %0, %1;" : "=r"(u) : "f"(x));
    return u;
}
__device__ __forceinline__ float tanh_fast(float x) {
    float y;
    asm("tanh.approx.f32 %0, %1;" : "=f"(y) : "f"(x));
    return y;
}
__device__ __forceinline__ void mma_m16n8k8(float* d, const uint32_t* a,
                                            const uint32_t* b) {
    asm volatile(
        "mma.sync.aligned.m16n8k8.row.col.f32.tf32.tf32.f32 "
        "{%0,%1,%2,%3}, {%4,%5,%6,%7}, {%8,%9}, {%0,%1,%2,%3};"
        : "+f"(d[0]), "+f"(d[1]), "+f"(d[2]), "+f"(d[3])
        : "r"(a[0]), "r"(a[1]), "r"(a[2]), "r"(a[3]), "r"(b[0]), "r"(b[1]));
}

// ==================== merged prep kernel ====================
__global__ void __launch_bounds__(256) prep_all(
    const float* __restrict__ bq, const float* __restrict__ Wq_h,
    const float* __restrict__ bk, const float* __restrict__ Wk_h,
    const float* __restrict__ b_h, const float* __restrict__ Wq,
    const float* __restrict__ Wk, const float* __restrict__ Wo) {
    __shared__ float sm[2][64][68];
    const int bx = blockIdx.x, tid = threadIdx.x;
    if (bx < 4) {
        int i = bx * 256 + tid;
        int side = i >> 9, col = i & 511, h = col >> 6, e = col & 63;
        const float* bb = side ? bk : bq;
        const float* Wh = (side ? Wk_h : Wq_h) + h * 4096;
        float s = 0.f;
#pragma unroll 8
        for (int d = 0; d < 64; d++) s += bb[h * 64 + d] * Wh[d * 64 + e];
        if (side) g_biasK[col] = s + b_h[col];
        else      g_biasQ[col] = s;
    } else if (bx < 132) {
        int q = bx - 4;
        int side = q >> 6;
        q &= 63;
        int h = q >> 3, k0 = (q & 7) * 64;
        const float* W = side ? Wk : Wq;
        const float* Wh = (side ? Wk_h : Wq_h) + h * 4096;
        float* C = (side ? g_WkEffT : g_WqEffT) + h * 64 * 512;
#pragma unroll
        for (int r = 0; r < 4; r++) {
            int idx = tid + r * 256;
            int row = idx >> 4, c4 = (idx & 15) << 2;
            *(float4*)&sm[0][row][c4] = *(const float4*)&W[(long)(k0 + row) * 512 + h * 64 + c4];
            *(float4*)&sm[1][row][c4] = *(const float4*)&Wh[row * 64 + c4];
        }
        __syncthreads();
        const int tmm = (tid >> 4) * 4, tnn = (tid & 15) * 4;
        float acc[4][4] = {};
#pragma unroll 8
        for (int d = 0; d < 64; d++) {
            float a[4], b[4];
#pragma unroll
            for (int i = 0; i < 4; i++) a[i] = sm[0][tmm + i][d];
            *(float4*)b = *(const float4*)&sm[1][d][tnn];
#pragma unroll
            for (int i = 0; i < 4; i++)
#pragma unroll
                for (int j = 0; j < 4; j++) acc[i][j] += a[i] * b[j];
        }
#pragma unroll
        for (int i = 0; i < 4; i++)
#pragma unroll
            for (int j = 0; j < 4; j++)
                C[(long)(tnn + j) * 512 + k0 + tmm + i] = acc[i][j];
    } else {
        int q = bx - 132;
        int zz = q >> 8;
        q &= 255;
        int by = q >> 4, bxx = q & 15;
        const float* S = zz ? Wo : Wk;
        float* D = zz ? g_WoT : g_WkT;
        float (*t)[33] = (float(*)[33]) & sm[0][0][0];
        int lx = tid & 31, ly = tid >> 5;
        int x = bxx * 32 + lx, y0 = by * 32;
#pragma unroll
        for (int r = ly; r < 32; r += 8) t[r][lx] = S[(long)(y0 + r) * 512 + x];
        __syncthreads();
        int xo = y0 + lx;
#pragma unroll
        for (int r = ly; r < 32; r += 8) D[(long)(bxx * 32 + r) * 512 + xo] = t[lx][r];
    }
}

// ==================== tf32 mma.sync GEMM core ====================
// Double-buffered smem, 2-chunk register prefetch, FULLY UNROLLED chunk loop
// (all slot/buffer indices compile-time -> no local-memory demotion).
// K-chunk 32. Tile MT x 64 (MT in {32,64}), 8 warps 2x4.
// C = A[Mx512] @ B^T (B K-major [512n][512k]) + bias.
// mode 0: row-major C. mode 1: [z][n&63][t] scatter. mode 2: [z][t][n&63].
template <int MT>
__device__ __forceinline__ void gemm_core(
    uint32_t* As, uint32_t* Bs,  // As: 2*(MT/16*4*128), Bs: 2*2048
    const float* __restrict__ A, const float* __restrict__ B,
    const float* __restrict__ bias, float* __restrict__ C,
    int m0, int n0, int mode) {
    constexpr int MI = MT / 32;          // mma m-tiles per warp
    constexpr int AR = MT / 32;          // A float4s per thread per chunk
    constexpr int ASTRIDE = (MT / 16) * 4 * 128;
    const int tid = threadIdx.x;
    const int wid = tid >> 5, lane = tid & 31;
    const int wm = wid >> 2, wn = wid & 3;

    float4 apf[2][AR], bpf[2][2];

    // addresses precomputed once
    const int arow = tid >> 3, ac4 = (tid & 7) << 2;
    const int arow2 = (tid + 256) >> 3;

#define LDG_CH(ch, slot)                                                          \
    {                                                                             \
        int k0 = (ch) << 5;                                                       \
        apf[slot][0] = *(const float4*)&A[(long)(m0 + arow) * 512 + k0 + ac4];    \
        if (AR > 1)                                                               \
            apf[slot][AR - 1] =                                                   \
                *(const float4*)&A[(long)(m0 + arow2) * 512 + k0 + ac4];          \
        bpf[slot][0] = *(const float4*)&B[(long)(n0 + arow) * 512 + k0 + ac4];    \
        bpf[slot][1] = *(const float4*)&B[(long)(n0 + arow2) * 512 + k0 + ac4];   \
    }

    auto sts_one_a = [&](int buf, int row, float4 v) {
        int ks = ac4 >> 3, chi = (ac4 >> 2) & 1;
        int mt = row >> 4, rlo = row & 15;
        int reg = (rlo >> 3) + (chi << 1);
        int off = buf * ASTRIDE + (mt * 4 + ks) * 128 + (rlo & 7) * 16 + reg;
        As[off + 0] = f2tf32(v.x);
        As[off + 4] = f2tf32(v.y);
        As[off + 8] = f2tf32(v.z);
        As[off + 12] = f2tf32(v.w);
    };
    auto sts_one_b = [&](int buf, int row, float4 v) {
        int ks = ac4 >> 3, chi = (ac4 >> 2) & 1;
        int nt = row >> 3, g = row & 7;
        int off = buf * 2048 + (nt * 4 + ks) * 64 + g * 8 + chi;
        Bs[off + 0] = f2tf32(v.x);
        Bs[off + 2] = f2tf32(v.y);
        Bs[off + 4] = f2tf32(v.z);
        Bs[off + 6] = f2tf32(v.w);
    };

#define STS_CH(slot, buf)                                  \
    {                                                      \
        sts_one_a(buf, arow, apf[slot][0]);                \
        if (AR > 1) sts_one_a(buf, arow2, apf[slot][AR - 1]); \
        sts_one_b(buf, arow, bpf[slot][0]);                \
        sts_one_b(buf, arow2, bpf[slot][1]);               \
    }

    float acc[MI][2][4] = {};
    auto compute = [&](int buf) {
#pragma unroll
        for (int ks = 0; ks < 4; ks++) {
            uint32_t a[MI][4], b[2][2];
#pragma unroll
            for (int i = 0; i < MI; i++) {
                int mt = wm * MI + i;
                uint4 v = *(const uint4*)&As[buf * ASTRIDE + (mt * 4 + ks) * 128 + lane * 4];
                a[i][0] = v.x; a[i][1] = v.y; a[i][2] = v.z; a[i][3] = v.w;
            }
#pragma unroll
            for (int j = 0; j < 2; j++) {
                int nt = wn * 2 + j;
                uint2 v = *(const uint2*)&Bs[buf * 2048 + (nt * 4 + ks) * 64 + lane * 2];
                b[j][0] = v.x; b[j][1] = v.y;
            }
#pragma unroll
            for (int i = 0; i < MI; i++)
#pragma unroll
                for (int j = 0; j < 2; j++) mma_m16n8k8(acc[i][j], a[i], b[j]);
        }
    };

    // software pipeline: ldg depth 2, smem depth 2; all indices static
    LDG_CH(0, 0);
    STS_CH(0, 0);
    LDG_CH(1, 1);
    __syncthreads();
#pragma unroll
    for (int ch = 0; ch < 16; ch++) {
        if (ch + 2 < 16) LDG_CH(ch + 2, ch & 1);
        compute(ch & 1);
        if (ch + 1 < 16) STS_CH((ch + 1) & 1, (ch + 1) & 1);
        __syncthreads();
    }
#undef LDG_CH
#undef STS_CH

    const int g = lane >> 2, t4 = lane & 3;
#pragma unroll
    for (int i = 0; i < MI; i++)
#pragma unroll
        for (int j = 0; j < 2; j++) {
            int m = m0 + wm * (MI * 16) + i * 16 + g;
            int n = n0 + wn * 16 + j * 8 + t4 * 2;
            float c0 = acc[i][j][0], c1 = acc[i][j][1];
            float c2 = acc[i][j][2], c3 = acc[i][j][3];
            if (bias) {
                float b0 = bias[n], b1 = bias[n + 1];
                c0 += b0; c1 += b1; c2 += b0; c3 += b1;
            }
            if (mode == 0) {
                *(float2*)&C[(long)m * 512 + n] = make_float2(c0, c1);
                *(float2*)&C[(long)(m + 8) * 512 + n] = make_float2(c2, c3);
            } else if (mode == 1) {
                int bb = m >> 9, t = m & 511;
                long base0 = ((long)((bb << 3) + (n >> 6)) * 64 + (n & 63)) * 512;
                C[base0 + t] = c0;
                C[base0 + 512 + t] = c1;
                C[base0 + t + 8] = c2;
                C[base0 + 512 + t + 8] = c3;
            } else {
                int bb = m >> 9, t = m & 511;
                long r0 = ((long)((bb << 3) + (n >> 6)) * 512 + t) * 64 + (n & 63);
                *(float2*)&C[r0] = make_float2(c0, c1);
                *(float2*)&C[r0 + 8 * 64] = make_float2(c2, c3);
            }
        }
}

// three projections in one launch (z = task), 64x64 tiles (grid 384)
__global__ void __launch_bounds__(256) proj_mma(
    const float* __restrict__ query, const float* __restrict__ key,
    const float* __restrict__ bk) {
    __shared__ uint32_t As[2][2048], Bs[2][2048];  // 32 KB
    int task = blockIdx.z;
    int m0 = blockIdx.y * 64, n0 = blockIdx.x * 64;
    if (task == 0)
        gemm_core<64>(&As[0][0], &Bs[0][0], query, g_WqEffT, g_biasQ, g_qhE, m0, n0, 1);
    else if (task == 1)
        gemm_core<64>(&As[0][0], &Bs[0][0], key, g_WkEffT, g_biasK, g_khbE, m0, n0, 1);
    else
        gemm_core<64>(&As[0][0], &Bs[0][0], key, g_WkT, bk, g_KpR, m0, n0, 2);
}
// output projection, 32x64 tiles -> 256 CTAs
__global__ void __launch_bounds__(256) outg_mma(
    const float* __restrict__ bo, float* __restrict__ out) {
    __shared__ uint32_t As[2][1024], Bs[2][2048];  // 24 KB
    gemm_core<32>(&As[0][0], &Bs[0][0], g_merged, g_WoT, bo, out,
                  blockIdx.y * 32, blockIdx.x * 64, 0);
}

// ==================== fused score + online-softmax + AV (round-7 version) ====
// grid (16 t-tiles, 16 z). Per CTA: rows t0..t0+31 of one (b,h).
__global__ void __launch_bounds__(256) fused_attn(const float* __restrict__ va) {
    const int t0 = blockIdx.x * 32;
    const int z = blockIdx.y;
    const int b = z >> 3, h = z & 7;
    __shared__ float qse[64][36];   // [e][t]
    __shared__ float kse[64][68];   // [e][s]; rows 0..31 reused as p[t][s]
    __shared__ float kp[64][68];    // [s][d]
    __shared__ float vsh[64];
    const int tid = threadIdx.x;
    const float* qbase = g_qhE + (long)z * 32768;
    const float* kbase = g_khbE + (long)z * 32768;
    const float* kpbase = g_KpR + (long)z * 32768;

#pragma unroll
    for (int r = 0; r < 2; r++) {
        int idx = tid + r * 256;
        int row = idx >> 3, c4 = (idx & 7) << 2;
        *(float4*)&qse[row][c4] = *(const float4*)&qbase[(long)row * 512 + t0 + c4];
    }
    if (tid < 64) vsh[tid] = va[h * 64 + tid];

    const int tm = (tid >> 4) * 2, tn = (tid & 15) * 4;
    float out[2][4] = {};
    float mrow[2] = {-1e30f, -1e30f};
    float lrow[2] = {0.f, 0.f};
    float* pbuf = &kse[0][0];

    for (int c = 0; c < 8; c++) {
        const int s0 = c * 64;
        __syncthreads();  // prior chunk consumers done with kse/kp
#pragma unroll
        for (int r = 0; r < 4; r++) {
            int idx = tid + r * 256;
            int row = idx >> 4, c4 = (idx & 15) << 2;
            *(float4*)&kse[row][c4] = *(const float4*)&kbase[(long)row * 512 + s0 + c4];
            *(float4*)&kp[row][c4] = *(const float4*)&kpbase[(long)(s0 + row) * 64 + c4];
        }
        __syncthreads();

        float sc[2][4] = {};
#pragma unroll 8
        for (int e = 0; e < 64; e++) {
            float vv = vsh[e];
            float2 q2 = *(const float2*)&qse[e][tm];
            float4 kv = *(const float4*)&kse[e][tn];
            sc[0][0] += vv * tanh_fast(q2.x + kv.x);
            sc[0][1] += vv * tanh_fast(q2.x + kv.y);
            sc[0][2] += vv * tanh_fast(q2.x + kv.z);
            sc[0][3] += vv * tanh_fast(q2.x + kv.w);
            sc[1][0] += vv * tanh_fast(q2.y + kv.x);
            sc[1][1] += vv * tanh_fast(q2.y + kv.y);
            sc[1][2] += vv * tanh_fast(q2.y + kv.z);
            sc[1][3] += vv * tanh_fast(q2.y + kv.w);
        }

        float rm[2], rs[2], alpha[2];
#pragma unroll
        for (int i = 0; i < 2; i++)
            rm[i] = fmaxf(fmaxf(sc[i][0], sc[i][1]), fmaxf(sc[i][2], sc[i][3]));
#pragma unroll
        for (int o = 8; o; o >>= 1) {
            rm[0] = fmaxf(rm[0], __shfl_xor_sync(0xffffffffu, rm[0], o));
            rm[1] = fmaxf(rm[1], __shfl_xor_sync(0xffffffffu, rm[1], o));
        }
#pragma unroll
        for (int i = 0; i < 2; i++) {
            float mn = fmaxf(mrow[i], rm[i]);
            alpha[i] = __expf(mrow[i] - mn);
            mrow[i] = mn;
#pragma unroll
            for (int j = 0; j < 4; j++) sc[i][j] = __expf(sc[i][j] - mn);
            rs[i] = (sc[i][0] + sc[i][1]) + (sc[i][2] + sc[i][3]);
        }
#pragma unroll
        for (int o = 8; o; o >>= 1) {
            rs[0] += __shfl_xor_sync(0xffffffffu, rs[0], o);
            rs[1] += __shfl_xor_sync(0xffffffffu, rs[1], o);
        }
#pragma unroll
        for (int i = 0; i < 2; i++) {
            lrow[i] = lrow[i] * alpha[i] + rs[i];
#pragma unroll
            for (int j = 0; j < 4; j++) out[i][j] *= alpha[i];
        }
        __syncthreads();  // all kse reads finished
        *(float4*)&pbuf[tm * 68 + tn] = make_float4(sc[0][0], sc[0][1], sc[0][2], sc[0][3]);
        *(float4*)&pbuf[(tm + 1) * 68 + tn] = make_float4(sc[1][0], sc[1][1], sc[1][2], sc[1][3]);
        __syncthreads();

#pragma unroll 4
        for (int s = 0; s < 64; s++) {
            float p0 = pbuf[tm * 68 + s];
            float p1 = pbuf[(tm + 1) * 68 + s];
            float4 kv = *(const float4*)&kp[s][tn];
            out[0][0] += p0 * kv.x; out[0][1] += p0 * kv.y;
            out[0][2] += p0 * kv.z; out[0][3] += p0 * kv.w;
            out[1][0] += p1 * kv.x; out[1][1] += p1 * kv.y;
            out[1][2] += p1 * kv.z; out[1][3] += p1 * kv.w;
        }
    }

    float inv0 = __fdividef(1.f, lrow[0]);
    float inv1 = __fdividef(1.f, lrow[1]);
    long r0 = (long)(b * 512 + t0 + tm) * 512 + h * 64 + tn;
    *(float4*)&g_merged[r0] =
        make_float4(out[0][0] * inv0, out[0][1] * inv0, out[0][2] * inv0, out[0][3] * inv0);
    *(float4*)&g_merged[r0 + 512] =
        make_float4(out[1][0] * inv1, out[1][1] * inv1, out[1][2] * inv1, out[1][3] * inv1);
}

// ---------------- launcher ----------------
extern "C" void kernel_launch(void* const* d_in, const int* in_sizes, int n_in,
                              void* d_out, int out_size) {
    const float* query = (const float*)d_in[0];
    const float* key   = (const float*)d_in[1];
    const float* Wq   = (const float*)d_in[3];
    const float* bq   = (const float*)d_in[4];
    const float* Wk   = (const float*)d_in[5];
    const float* bk   = (const float*)d_in[6];
    const float* Wq_h = (const float*)d_in[9];
    const float* Wk_h = (const float*)d_in[10];
    const float* va_h = (const float*)d_in[11];
    const float* b_h  = (const float*)d_in[12];
    const float* Wo   = (const float*)d_in[13];
    const float* bo   = (const float*)d_in[14];
    float* out = (float*)d_out;

    prep_all<<<644, 256>>>(bq, Wq_h, bk, Wk_h, b_h, Wq, Wk, Wo);
    proj_mma<<<dim3(8, 16, 3), 256>>>(query, key, bk);
    fused_attn<<<dim3(16, 16), 256>>>(va_h);
    outg_mma<<<dim3(8, 32), 256>>>(bo, out);
}

// round 14
// speedup vs baseline: 1.3656x; 1.1308x over previous
#include <cuda_runtime.h>
#include <cstdint>

// ---------------- scratch (no allocations allowed) ----------------
__device__ float g_WqEffT[512 * 512];   // [n=h*64+e][k]
__device__ float g_WkEffT[512 * 512];
__device__ float g_WkT[512 * 512];
__device__ float g_WoT[512 * 512];
__device__ float g_biasQ[512];
__device__ float g_biasK[512];
__device__ float g_qhE[16 * 64 * 512];   // [z][e][t]
__device__ float g_khbE[16 * 64 * 512];  // [z][e][s]
__device__ float g_KpR[16 * 512 * 64];   // [z][s][d]
__device__ float g_part[64 * 512 * 64];  // [(z*4+sq)][t][d] unnormalized AV partial
__device__ float g_lpart[64 * 512];      // [(z*4+sq)][t] partial exp-sums
__device__ float g_merged[1024 * 512];   // [b*512+t][h*64+d]

__device__ __forceinline__ uint32_t f2tf32(float x) {
    uint32_t u;
    asm("cvt.rna.tf32.f32 %0, %1;" : "=r"(u) : "f"(x));
    return u;
}
__device__ __forceinline__ float tanh_fast(float x) {
    float y;
    asm("tanh.approx.f32 %0, %1;" : "=f"(y) : "f"(x));
    return y;
}
__device__ __forceinline__ void mma_m16n8k8(float* d, const uint32_t* a,
                                            const uint32_t* b) {
    asm volatile(
        "mma.sync.aligned.m16n8k8.row.col.f32.tf32.tf32.f32 "
        "{%0,%1,%2,%3}, {%4,%5,%6,%7}, {%8,%9}, {%0,%1,%2,%3};"
        : "+f"(d[0]), "+f"(d[1]), "+f"(d[2]), "+f"(d[3])
        : "r"(a[0]), "r"(a[1]), "r"(a[2]), "r"(a[3]), "r"(b[0]), "r"(b[1]));
}

// ==================== merged prep kernel ====================
__global__ void __launch_bounds__(256) prep_all(
    const float* __restrict__ bq, const float* __restrict__ Wq_h,
    const float* __restrict__ bk, const float* __restrict__ Wk_h,
    const float* __restrict__ b_h, const float* __restrict__ Wq,
    const float* __restrict__ Wk, const float* __restrict__ Wo) {
    __shared__ float sm[2][64][68];
    const int bx = blockIdx.x, tid = threadIdx.x;
    if (bx < 4) {
        int i = bx * 256 + tid;
        int side = i >> 9, col = i & 511, h = col >> 6, e = col & 63;
        const float* bb = side ? bk : bq;
        const float* Wh = (side ? Wk_h : Wq_h) + h * 4096;
        float s = 0.f;
#pragma unroll 8
        for (int d = 0; d < 64; d++) s += bb[h * 64 + d] * Wh[d * 64 + e];
        if (side) g_biasK[col] = s + b_h[col];
        else      g_biasQ[col] = s;
    } else if (bx < 132) {
        int q = bx - 4;
        int side = q >> 6;
        q &= 63;
        int h = q >> 3, k0 = (q & 7) * 64;
        const float* W = side ? Wk : Wq;
        const float* Wh = (side ? Wk_h : Wq_h) + h * 4096;
        float* C = (side ? g_WkEffT : g_WqEffT) + h * 64 * 512;
#pragma unroll
        for (int r = 0; r < 4; r++) {
            int idx = tid + r * 256;
            int row = idx >> 4, c4 = (idx & 15) << 2;
            *(float4*)&sm[0][row][c4] = *(const float4*)&W[(long)(k0 + row) * 512 + h * 64 + c4];
            *(float4*)&sm[1][row][c4] = *(const float4*)&Wh[row * 64 + c4];
        }
        __syncthreads();
        const int tmm = (tid >> 4) * 4, tnn = (tid & 15) * 4;
        float acc[4][4] = {};
#pragma unroll 8
        for (int d = 0; d < 64; d++) {
            float a[4], b[4];
#pragma unroll
            for (int i = 0; i < 4; i++) a[i] = sm[0][tmm + i][d];
            *(float4*)b = *(const float4*)&sm[1][d][tnn];
#pragma unroll
            for (int i = 0; i < 4; i++)
#pragma unroll
                for (int j = 0; j < 4; j++) acc[i][j] += a[i] * b[j];
        }
#pragma unroll
        for (int i = 0; i < 4; i++)
#pragma unroll
            for (int j = 0; j < 4; j++)
                C[(long)(tnn + j) * 512 + k0 + tmm + i] = acc[i][j];
    } else {
        int q = bx - 132;
        int zz = q >> 8;
        q &= 255;
        int by = q >> 4, bxx = q & 15;
        const float* S = zz ? Wo : Wk;
        float* D = zz ? g_WoT : g_WkT;
        float (*t)[33] = (float(*)[33]) & sm[0][0][0];
        int lx = tid & 31, ly = tid >> 5;
        int x = bxx * 32 + lx, y0 = by * 32;
#pragma unroll
        for (int r = ly; r < 32; r += 8) t[r][lx] = S[(long)(y0 + r) * 512 + x];
        __syncthreads();
        int xo = y0 + lx;
#pragma unroll
        for (int r = ly; r < 32; r += 8) D[(long)(bxx * 32 + r) * 512 + xo] = t[lx][r];
    }
}

// ==================== tf32 mma.sync GEMM core (R7 proven form, templated MT) ====
// Double-buffered smem, K-chunk 32, dynamic chunk loop, 1-deep register stage.
// Tile MT x 64 (MT in {32,64}), 8 warps 2x4.
// C = A[Mx512] @ B^T (B K-major [512n][512k]) + bias.
// mode 0: row-major C. mode 1: [z][n&63][t] scatter. mode 2: [z][t][n&63].
template <int MT>
__device__ __forceinline__ void gemm_core(
    uint32_t* As, uint32_t* Bs,  // As: 2*ASTRIDE, Bs: 2*2048
    const float* __restrict__ A, const float* __restrict__ B,
    const float* __restrict__ bias, float* __restrict__ C,
    int m0, int n0, int mode) {
    constexpr int MI = MT / 32;          // mma m-tiles per warp
    constexpr int AR = MT / 32;          // A float4s per thread per chunk
    constexpr int ASTRIDE = (MT / 16) * 4 * 128;
    const int tid = threadIdx.x;
    const int wid = tid >> 5, lane = tid & 31;
    const int wm = wid >> 2, wn = wid & 3;

    float4 apf[AR], bpf[2];
    auto ldg = [&](int ch) {
        int k0 = ch << 5;
#pragma unroll
        for (int r = 0; r < AR; r++) {
            int j = tid + 256 * r;
            int row = j >> 3, c4 = (j & 7) << 2;
            apf[r] = *(const float4*)&A[(long)(m0 + row) * 512 + k0 + c4];
        }
#pragma unroll
        for (int r = 0; r < 2; r++) {
            int j = tid + 256 * r;
            int row = j >> 3, c4 = (j & 7) << 2;
            bpf[r] = *(const float4*)&B[(long)(n0 + row) * 512 + k0 + c4];
        }
    };
    auto sts = [&](int buf) {
#pragma unroll
        for (int r = 0; r < AR; r++) {
            int j = tid + 256 * r;
            int row = j >> 3, c4 = (j & 7) << 2;
            int ks = c4 >> 3, chi = (c4 >> 2) & 1;
            int mt = row >> 4, rlo = row & 15;
            int reg = (rlo >> 3) + (chi << 1);
            int off = buf * ASTRIDE + (mt * 4 + ks) * 128 + (rlo & 7) * 16 + reg;
            As[off + 0] = f2tf32(apf[r].x);
            As[off + 4] = f2tf32(apf[r].y);
            As[off + 8] = f2tf32(apf[r].z);
            As[off + 12] = f2tf32(apf[r].w);
        }
#pragma unroll
        for (int r = 0; r < 2; r++) {
            int j = tid + 256 * r;
            int row = j >> 3, c4 = (j & 7) << 2;
            int ks = c4 >> 3, chi = (c4 >> 2) & 1;
            int nt = row >> 3, g = row & 7;
            int off = buf * 2048 + (nt * 4 + ks) * 64 + g * 8 + chi;
            Bs[off + 0] = f2tf32(bpf[r].x);
            Bs[off + 2] = f2tf32(bpf[r].y);
            Bs[off + 4] = f2tf32(bpf[r].z);
            Bs[off + 6] = f2tf32(bpf[r].w);
        }
    };

    float acc[MI][2][4] = {};
    auto compute = [&](int buf) {
#pragma unroll
        for (int ks = 0; ks < 4; ks++) {
            uint32_t a[MI][4], b[2][2];
#pragma unroll
            for (int i = 0; i < MI; i++) {
                int mt = wm * MI + i;
                uint4 v = *(const uint4*)&As[buf * ASTRIDE + (mt * 4 + ks) * 128 + lane * 4];
                a[i][0] = v.x; a[i][1] = v.y; a[i][2] = v.z; a[i][3] = v.w;
            }
#pragma unroll
            for (int j = 0; j < 2; j++) {
                int nt = wn * 2 + j;
                uint2 v = *(const uint2*)&Bs[buf * 2048 + (nt * 4 + ks) * 64 + lane * 2];
                b[j][0] = v.x; b[j][1] = v.y;
            }
#pragma unroll
            for (int i = 0; i < MI; i++)
#pragma unroll
                for (int j = 0; j < 2; j++) mma_m16n8k8(acc[i][j], a[i], b[j]);
        }
    };

    ldg(0);
    sts(0);
    __syncthreads();
    for (int ch = 0; ch < 16; ch++) {
        if (ch + 1 < 16) ldg(ch + 1);
        compute(ch & 1);
        if (ch + 1 < 16) sts((ch + 1) & 1);
        __syncthreads();
    }

    const int g = lane >> 2, t4 = lane & 3;
#pragma unroll
    for (int i = 0; i < MI; i++)
#pragma unroll
        for (int j = 0; j < 2; j++) {
            int m = m0 + wm * (MI * 16) + i * 16 + g;
            int n = n0 + wn * 16 + j * 8 + t4 * 2;
            float c0 = acc[i][j][0], c1 = acc[i][j][1];
            float c2 = acc[i][j][2], c3 = acc[i][j][3];
            if (bias) {
                float b0 = bias[n], b1 = bias[n + 1];
                c0 += b0; c1 += b1; c2 += b0; c3 += b1;
            }
            if (mode == 0) {
                *(float2*)&C[(long)m * 512 + n] = make_float2(c0, c1);
                *(float2*)&C[(long)(m + 8) * 512 + n] = make_float2(c2, c3);
            } else if (mode == 1) {
                int bb = m >> 9, t = m & 511;
                long base0 = ((long)((bb << 3) + (n >> 6)) * 64 + (n & 63)) * 512;
                C[base0 + t] = c0;
                C[base0 + 512 + t] = c1;
                C[base0 + t + 8] = c2;
                C[base0 + 512 + t + 8] = c3;
            } else {
                int bb = m >> 9, t = m & 511;
                long r0 = ((long)((bb << 3) + (n >> 6)) * 512 + t) * 64 + (n & 63);
                *(float2*)&C[r0] = make_float2(c0, c1);
                *(float2*)&C[r0 + 8 * 64] = make_float2(c2, c3);
            }
        }
}

// three projections in one launch (z = task), 64x64 tiles (grid 384)
__global__ void __launch_bounds__(256) proj_mma(
    const float* __restrict__ query, const float* __restrict__ key,
    const float* __restrict__ bk) {
    __shared__ uint32_t As[2][2048], Bs[2][2048];  // 32 KB
    int task = blockIdx.z;
    int m0 = blockIdx.y * 64, n0 = blockIdx.x * 64;
    if (task == 0)
        gemm_core<64>(&As[0][0], &Bs[0][0], query, g_WqEffT, g_biasQ, g_qhE, m0, n0, 1);
    else if (task == 1)
        gemm_core<64>(&As[0][0], &Bs[0][0], key, g_WkEffT, g_biasK, g_khbE, m0, n0, 1);
    else
        gemm_core<64>(&As[0][0], &Bs[0][0], key, g_WkT, bk, g_KpR, m0, n0, 2);
}
// output projection, 32x64 tiles -> 256 CTAs
__global__ void __launch_bounds__(256) outg_mma(
    const float* __restrict__ bo, float* __restrict__ out) {
    __shared__ uint32_t As[2][1024], Bs[2][2048];  // 24 KB
    gemm_core<32>(&As[0][0], &Bs[0][0], g_merged, g_WoT, bo, out,
                  blockIdx.y * 32, blockIdx.x * 64, 0);
}

// ==================== fused score + exp + AV, s-split partials ====================
// grid (16 t-tiles, 16 z, 4 s-quarters). Per CTA: rows t0..t0+31 of one (b,h),
// s-chunks [2*sq, 2*sq+2). Scores are bounded (|score| ~< 1.5), so exp is taken
// WITHOUT max-subtraction; partials combine by plain summation in combine_attn.
__global__ void __launch_bounds__(256) fused_attn(const float* __restrict__ va) {
    const int t0 = blockIdx.x * 32;
    const int z = blockIdx.y;
    const int sq = blockIdx.z;
    const int h = z & 7;
    __shared__ float qse[64][36];   // [e][t]
    __shared__ float kse[64][68];   // [e][s]; rows 0..31 reused as p[t][s]
    __shared__ float kp[64][68];    // [s][d]
    __shared__ float vsh[64];
    const int tid = threadIdx.x;
    const float* qbase = g_qhE + (long)z * 32768;
    const float* kbase = g_khbE + (long)z * 32768;
    const float* kpbase = g_KpR + (long)z * 32768;

#pragma unroll
    for (int r = 0; r < 2; r++) {
        int idx = tid + r * 256;
        int row = idx >> 3, c4 = (idx & 7) << 2;
        *(float4*)&qse[row][c4] = *(const float4*)&qbase[(long)row * 512 + t0 + c4];
    }
    if (tid < 64) vsh[tid] = va[h * 64 + tid];

    const int tm = (tid >> 4) * 2, tn = (tid & 15) * 4;
    float out[2][4] = {};
    float lrow[2] = {0.f, 0.f};
    float* pbuf = &kse[0][0];

    for (int c = sq * 2; c < sq * 2 + 2; c++) {
        const int s0 = c * 64;
        __syncthreads();  // prior chunk consumers done with kse/kp
#pragma unroll
        for (int r = 0; r < 4; r++) {
            int idx = tid + r * 256;
            int row = idx >> 4, c4 = (idx & 15) << 2;
            *(float4*)&kse[row][c4] = *(const float4*)&kbase[(long)row * 512 + s0 + c4];
            *(float4*)&kp[row][c4] = *(const float4*)&kpbase[(long)(s0 + row) * 64 + c4];
        }
        __syncthreads();

        float sc[2][4] = {};
#pragma unroll 8
        for (int e = 0; e < 64; e++) {
            float vv = vsh[e];
            float2 q2 = *(const float2*)&qse[e][tm];
            float4 kv = *(const float4*)&kse[e][tn];
            sc[0][0] += vv * tanh_fast(q2.x + kv.x);
            sc[0][1] += vv * tanh_fast(q2.x + kv.y);
            sc[0][2] += vv * tanh_fast(q2.x + kv.z);
            sc[0][3] += vv * tanh_fast(q2.x + kv.w);
            sc[1][0] += vv * tanh_fast(q2.y + kv.x);
            sc[1][1] += vv * tanh_fast(q2.y + kv.y);
            sc[1][2] += vv * tanh_fast(q2.y + kv.z);
            sc[1][3] += vv * tanh_fast(q2.y + kv.w);
        }

        // p = exp(score) directly (bounded scores; no max subtraction needed)
#pragma unroll
        for (int i = 0; i < 2; i++) {
#pragma unroll
            for (int j = 0; j < 4; j++) sc[i][j] = __expf(sc[i][j]);
            lrow[i] += (sc[i][0] + sc[i][1]) + (sc[i][2] + sc[i][3]);
        }

        __syncthreads();  // all kse reads finished (pbuf aliases kse)
        *(float4*)&pbuf[tm * 68 + tn] = make_float4(sc[0][0], sc[0][1], sc[0][2], sc[0][3]);
        *(float4*)&pbuf[(tm + 1) * 68 + tn] = make_float4(sc[1][0], sc[1][1], sc[1][2], sc[1][3]);
        __syncthreads();

#pragma unroll 4
        for (int s = 0; s < 64; s++) {
            float p0 = pbuf[tm * 68 + s];
            float p1 = pbuf[(tm + 1) * 68 + s];
            float4 kv = *(const float4*)&kp[s][tn];
            out[0][0] += p0 * kv.x; out[0][1] += p0 * kv.y;
            out[0][2] += p0 * kv.z; out[0][3] += p0 * kv.w;
            out[1][0] += p1 * kv.x; out[1][1] += p1 * kv.y;
            out[1][2] += p1 * kv.z; out[1][3] += p1 * kv.w;
        }
    }

    // reduce lrow across the 16 threads sharing each row pair, write partials
#pragma unroll
    for (int o = 8; o; o >>= 1) {
        lrow[0] += __shfl_xor_sync(0xffffffffu, lrow[0], o);
        lrow[1] += __shfl_xor_sync(0xffffffffu, lrow[1], o);
    }
    long pb0 = ((long)((z << 2) + sq) * 512 + t0 + tm) * 64 + tn;
    *(float4*)&g_part[pb0] = make_float4(out[0][0], out[0][1], out[0][2], out[0][3]);
    *(float4*)&g_part[pb0 + 64] = make_float4(out[1][0], out[1][1], out[1][2], out[1][3]);
    if ((tid & 15) == 0) {
        int lb = ((z << 2) + sq) * 512 + t0 + tm;
        g_lpart[lb] = lrow[0];
        g_lpart[lb + 1] = lrow[1];
    }
}

// ==================== combine partials -> g_merged ====================
__global__ void __launch_bounds__(256) combine_attn() {
    int idx = blockIdx.x * 256 + threadIdx.x;  // 16*512*64 = 524288
    int col = idx & 63;
    int t = (idx >> 6) & 511;
    int z = idx >> 15;
    int b = z >> 3, h = z & 7;
    float s = 0.f, l = 0.f;
#pragma unroll
    for (int q = 0; q < 4; q++) {
        s += g_part[(((long)((z << 2) + q) * 512 + t) << 6) + col];
        l += g_lpart[((z << 2) + q) * 512 + t];
    }
    g_merged[(long)(b * 512 + t) * 512 + h * 64 + col] = s * __fdividef(1.f, l);
}

// ---------------- launcher ----------------
extern "C" void kernel_launch(void* const* d_in, const int* in_sizes, int n_in,
                              void* d_out, int out_size) {
    const float* query = (const float*)d_in[0];
    const float* key   = (const float*)d_in[1];
    const float* Wq   = (const float*)d_in[3];
    const float* bq   = (const float*)d_in[4];
    const float* Wk   = (const float*)d_in[5];
    const float* bk   = (const float*)d_in[6];
    const float* Wq_h = (const float*)d_in[9];
    const float* Wk_h = (const float*)d_in[10];
    const float* va_h = (const float*)d_in[11];
    const float* b_h  = (const float*)d_in[12];
    const float* Wo   = (const float*)d_in[13];
    const float* bo   = (const float*)d_in[14];
    float* out = (float*)d_out;

    prep_all<<<644, 256>>>(bq, Wq_h, bk, Wk_h, b_h, Wq, Wk, Wo);
    proj_mma<<<dim3(8, 16, 3), 256>>>(query, key, bk);
    fused_attn<<<dim3(16, 16, 4), 256>>>(va_h);
    combine_attn<<<2048, 256>>>();
    outg_mma<<<dim3(8, 32), 256>>>(bo, out);
}